// round 5
// baseline (speedup 1.0000x reference)
#include <cuda_runtime.h>
#include <cstdint>
#include <cstddef>

#define S_   250
#define N_   200
#define MAXC 16
#define H_   64
#define HID_ 512
#define BN_  32
#define NPED (S_*N_)

// ---- scratch (static __device__ arrays: allocation-free) ----
__device__ __align__(16) static float g_Y[(size_t)NPED * HID_];   // h @ W1[:64]
__device__               static int   g_sel[NPED * MAXC];         // ranks
__device__ __align__(16) static float g_wpe[2 * HID_];            // W_pos @ W1[64:]
__device__ __align__(16) static float g_b1p[HID_];                // b1 + b_pos @ W1[64:]

// =====================================================================
// tiny precompute: wpe, folded bias
// =====================================================================
__global__ void prep_kernel(const float* __restrict__ W_pos, const float* __restrict__ b_pos,
                            const float* __restrict__ W1,    const float* __restrict__ b1) {
    int t = threadIdx.x; // 512 threads
    float s0 = 0.f, s1 = 0.f, sb = 0.f;
    for (int e = 0; e < 64; ++e) {
        float w = W1[(size_t)(64 + e) * HID_ + t];
        s0 += W_pos[e] * w;
        s1 += W_pos[64 + e] * w;
        sb += b_pos[e] * w;
    }
    g_wpe[t] = s0;
    g_wpe[HID_ + t] = s1;
    g_b1p[t] = b1[t] + sb;
}

// =====================================================================
// ranks: sel[s,i,m] = #{ j : d_j<d_m or (d_j==d_m and j<m) }  (stable argsort^2)
// one warp per ped i; exact fp32 replica of sqrt(dx*dx+dy*dy), no fma
// =====================================================================
__device__ __forceinline__ float distf(const float* px, const float* py,
                                       int j, float xi, float yi) {
    float dx = px[j] - xi;
    float dy = py[j] - yi;
    return __fsqrt_rn(__fadd_rn(__fmul_rn(dx, dx), __fmul_rn(dy, dy)));
}

__global__ void rank_kernel(const float* __restrict__ lp) {
    int s = blockIdx.y;
    __shared__ float px[N_], py[N_];
    int tid = threadIdx.x;
    for (int j = tid; j < N_; j += 256) {
        px[j] = lp[(size_t)(s * N_ + j) * 2];
        py[j] = lp[(size_t)(s * N_ + j) * 2 + 1];
    }
    __syncthreads();
    int w = tid >> 5, lane = tid & 31;
    int i = blockIdx.x * 8 + w;
    float xi = px[i], yi = py[i];

    float dl = distf(px, py, lane, xi, yi);
    float dm[MAXC];
#pragma unroll
    for (int m = 0; m < MAXC; ++m) dm[m] = __shfl_sync(0xffffffffu, dl, m);

    int cnt[MAXC];
#pragma unroll
    for (int m = 0; m < MAXC; ++m) cnt[m] = 0;
    for (int j = lane; j < N_; j += 32) {
        float d = distf(px, py, j, xi, yi);
#pragma unroll
        for (int m = 0; m < MAXC; ++m)
            cnt[m] += (int)((d < dm[m]) || (d == dm[m] && j < m));
    }
    int myr = 0;
#pragma unroll
    for (int m = 0; m < MAXC; ++m) {
        int tot = __reduce_add_sync(0xffffffffu, cnt[m]);
        if (lane == m) myr = tot;
    }
    if (lane < MAXC) g_sel[(s * N_ + i) * MAXC + lane] = myr;
}

// =====================================================================
// Y = h @ W1[0:64,:]   (50000x64 @ 64x512), 64x64 tiles, 256 thr, 4x4 reg tile
// =====================================================================
__global__ void y_kernel(const float* __restrict__ h, const float* __restrict__ W1) {
    __shared__ __align__(16) float Ash[64 * 65];
    __shared__ __align__(16) float Bsh[64 * 64];
    int tid = threadIdx.x;
    int row0 = blockIdx.x * 64;
    int c0   = blockIdx.y * 64;
#pragma unroll
    for (int q = 0; q < 4; ++q) {
        int idx4 = tid + 256 * q;            // 1024 float4 slots
        int row = idx4 >> 4, k4 = (idx4 & 15) << 2;
        float4 v = make_float4(0.f, 0.f, 0.f, 0.f);
        if (row0 + row < NPED) v = *(const float4*)&h[(size_t)(row0 + row) * H_ + k4];
        Ash[row * 65 + k4 + 0] = v.x; Ash[row * 65 + k4 + 1] = v.y;
        Ash[row * 65 + k4 + 2] = v.z; Ash[row * 65 + k4 + 3] = v.w;
    }
#pragma unroll
    for (int q = 0; q < 4; ++q) {
        int idx4 = tid + 256 * q;
        int k = idx4 >> 4, c4 = (idx4 & 15) << 2;
        *(float4*)&Bsh[k * 64 + c4] = *(const float4*)&W1[(size_t)k * HID_ + c0 + c4];
    }
    __syncthreads();
    int rg = tid >> 4, cg = tid & 15;
    float acc[4][4] = {};
#pragma unroll 16
    for (int k = 0; k < 64; ++k) {
        float a[4];
#pragma unroll
        for (int r = 0; r < 4; ++r) a[r] = Ash[(rg * 4 + r) * 65 + k];
        float4 b = *(const float4*)&Bsh[k * 64 + cg * 4];
#pragma unroll
        for (int r = 0; r < 4; ++r) {
            acc[r][0] += a[r] * b.x; acc[r][1] += a[r] * b.y;
            acc[r][2] += a[r] * b.z; acc[r][3] += a[r] * b.w;
        }
    }
#pragma unroll
    for (int r = 0; r < 4; ++r) {
        int row = row0 + rg * 4 + r;
        if (row < NPED)
            *(float4*)&g_Y[(size_t)row * HID_ + c0 + cg * 4] =
                make_float4(acc[r][0], acc[r][1], acc[r][2], acc[r][3]);
    }
}

// =====================================================================
// fused: gather + layer1 assembly + layer2 GEMM + attention pool
// block = (s, 8 peds) -> 128 rows x 32 cols; 128 thr, 4x8 reg tile, Kc=64
// =====================================================================
#define SM_FLOATS 12864

__global__ __launch_bounds__(128) void fused_kernel(
    const float* __restrict__ lp, const float* __restrict__ W2g,
    const float* __restrict__ b2g, const float* __restrict__ Wag,
    const float* __restrict__ bag, float* __restrict__ out) {
    extern __shared__ __align__(16) float sm[];
    float* X1   = sm;            // 128 x 65  (reused as X2: 128 x 33)
    float* W2c  = sm + 8320;     // 64 x 32
    float* wpe0 = sm + 10368;
    float* wpe1 = sm + 10880;
    float* b1p  = sm + 11392;
    float* px   = sm + 11904;
    float* py   = sm + 12104;
    float* fxs  = sm + 12304;
    float* fys  = sm + 12432;
    float* wsh  = sm + 12560;
    float* b2s  = sm + 12688;
    float* bats = sm + 12720;
    int*   yrs  = (int*)(sm + 12736);

    int tid = threadIdx.x;
    int s = blockIdx.y;
    int pg = blockIdx.x;
    int base = s * N_;

    for (int j = tid; j < N_; j += 128) {
        float2 p = *(const float2*)&lp[(size_t)(base + j) * 2];
        px[j] = p.x; py[j] = p.y;
    }
    for (int k = tid; k < HID_; k += 128) {
        wpe0[k] = g_wpe[k];
        wpe1[k] = g_wpe[HID_ + k];
        b1p[k]  = g_b1p[k];
    }
    if (tid < BN_)  b2s[tid]  = b2g[tid];
    if (tid < MAXC) bats[tid] = bag[tid];
    __syncthreads();

    {   // per-row gather info (row = tid = 8 peds x 16 neighbors)
        int p = tid >> 4;
        int i = pg * 8 + p;
        int r = g_sel[(base + i) * MAXC + (tid & 15)];
        yrs[tid] = base + r;
        fxs[tid] = px[r] - px[i];
        fys[tid] = py[r] - py[i];
    }
    __syncthreads();

    const int rg = tid >> 2;   // 32 row-groups of 4
    const int cg = tid & 3;    // 4 col-groups of 8
    float acc[4][8];
#pragma unroll
    for (int r = 0; r < 4; ++r)
#pragma unroll
        for (int c = 0; c < 8; ++c) acc[r][c] = 0.f;

    float fx = fxs[tid], fy = fys[tid];
    const float* yp = g_Y + (size_t)yrs[tid] * HID_;

    for (int kc = 0; kc < HID_; kc += 64) {
        // build X1 row tid for k in [0,64)
#pragma unroll
        for (int k4 = 0; k4 < 64; k4 += 4) {
            float4 y  = *(const float4*)&yp[kc + k4];
            float4 w0 = *(const float4*)&wpe0[kc + k4];
            float4 w1 = *(const float4*)&wpe1[kc + k4];
            float4 bb = *(const float4*)&b1p[kc + k4];
            X1[tid*65 + k4+0] = fmaxf(fmaf(fx, w0.x, fmaf(fy, w1.x, y.x + bb.x)), 0.f);
            X1[tid*65 + k4+1] = fmaxf(fmaf(fx, w0.y, fmaf(fy, w1.y, y.y + bb.y)), 0.f);
            X1[tid*65 + k4+2] = fmaxf(fmaf(fx, w0.z, fmaf(fy, w1.z, y.z + bb.z)), 0.f);
            X1[tid*65 + k4+3] = fmaxf(fmaf(fx, w0.w, fmaf(fy, w1.w, y.w + bb.w)), 0.f);
        }
        // W2 chunk: 2048 floats = 512 float4
#pragma unroll
        for (int q = 0; q < 4; ++q) {
            int idx = tid + q * 128;
            *(float4*)&W2c[idx * 4] = *(const float4*)&W2g[(size_t)kc * 32 + idx * 4];
        }
        __syncthreads();
#pragma unroll 8
        for (int k = 0; k < 64; ++k) {
            float a[4];
#pragma unroll
            for (int r = 0; r < 4; ++r) a[r] = X1[(rg * 4 + r) * 65 + k];
            float4 b0 = *(const float4*)&W2c[k * 32 + cg * 8];
            float4 b1v = *(const float4*)&W2c[k * 32 + cg * 8 + 4];
            float b[8] = {b0.x, b0.y, b0.z, b0.w, b1v.x, b1v.y, b1v.z, b1v.w};
#pragma unroll
            for (int r = 0; r < 4; ++r)
#pragma unroll
                for (int c = 0; c < 8; ++c)
                    acc[r][c] = fmaf(a[r], b[c], acc[r][c]);
        }
        __syncthreads();
    }

    // X2 = relu(acc + b2), stride 33 (aliases X1; all reads done)
    float* X2 = sm;
#pragma unroll
    for (int r = 0; r < 4; ++r) {
        int row = rg * 4 + r;
#pragma unroll
        for (int c = 0; c < 8; ++c) {
            int col = cg * 8 + c;
            X2[row * 33 + col] = fmaxf(acc[r][c] + b2s[col], 0.f);
        }
    }
    __syncthreads();

    // logits: thread (p = tid>>4, t = tid&15)
    int p = tid >> 4, t = tid & 15;
    float lg = bats[t];
    const float* wa = Wag + t;
#pragma unroll 4
    for (int k = 0; k < 512; ++k) {
        int m = k >> 5, c = k & 31;
        lg = fmaf(X2[(p * 16 + m) * 33 + c], __ldg(&wa[k * 16]), lg);
    }
    // softmax over 16-lane groups
    float mx = lg;
#pragma unroll
    for (int o = 8; o; o >>= 1) mx = fmaxf(mx, __shfl_xor_sync(0xffffffffu, mx, o, 16));
    float e = expf(lg - mx);
    float sum = e;
#pragma unroll
    for (int o = 8; o; o >>= 1) sum += __shfl_xor_sync(0xffffffffu, sum, o, 16);
    wsh[tid] = e / sum;
    __syncthreads();

    // weighted pool: 8 peds x 32 cols
    for (int o = tid; o < 256; o += 128) {
        int p2 = o >> 5, c = o & 31;
        float acc2 = 0.f;
#pragma unroll
        for (int m = 0; m < MAXC; ++m)
            acc2 = fmaf(X2[(p2 * 16 + m) * 33 + c], wsh[p2 * 16 + m], acc2);
        out[(size_t)(base + pg * 8 + p2) * BN_ + c] = acc2;
    }
}

extern "C" void kernel_launch(void* const* d_in, const int* in_sizes, int n_in,
                              void* d_out, int out_size) {
    const float* h_st  = (const float*)d_in[0];
    const float* lp    = (const float*)d_in[1];
    const float* W_pos = (const float*)d_in[2];
    const float* b_pos = (const float*)d_in[3];
    const float* W1    = (const float*)d_in[4];
    const float* b1    = (const float*)d_in[5];
    const float* W2    = (const float*)d_in[6];
    const float* b2    = (const float*)d_in[7];
    const float* Wa    = (const float*)d_in[8];
    const float* ba    = (const float*)d_in[9];
    float* out = (float*)d_out;

    cudaFuncSetAttribute(fused_kernel, cudaFuncAttributeMaxDynamicSharedMemorySize,
                         SM_FLOATS * (int)sizeof(float));

    prep_kernel<<<1, HID_>>>(W_pos, b_pos, W1, b1);
    rank_kernel<<<dim3(N_ / 8, S_), 256>>>(lp);
    y_kernel<<<dim3((NPED + 63) / 64, HID_ / 64), 256>>>(h_st, W1);
    fused_kernel<<<dim3(N_ / 8, S_), 128, SM_FLOATS * (int)sizeof(float)>>>(
        lp, W2, b2, Wa, ba, out);
}

// round 6
// speedup vs baseline: 1.1520x; 1.1520x over previous
#include <cuda_runtime.h>
#include <cstdint>
#include <cstddef>

#define S_   250
#define N_   200
#define MAXC 16
#define H_   64
#define HID_ 512
#define BN_  32
#define NPED (S_*N_)

// ---- scratch (static __device__ arrays: allocation-free) ----
__device__ __align__(16) static float g_Y[(size_t)NPED * HID_];   // h @ W1[:64]
__device__               static int   g_sel[NPED * MAXC];         // ranks
__device__ __align__(16) static float g_wpe[2 * HID_];            // W_pos @ W1[64:]
__device__ __align__(16) static float g_b1p[HID_];                // b1 + b_pos @ W1[64:]

// ---- packed f32x2 helpers ----
#define FMA2(d, a, b) asm("fma.rn.f32x2 %0, %1, %2, %0;" : "+l"(d) : "l"(a), "l"(b))
#define PACK_DUP(d, x) asm("mov.b64 %0, {%1, %1};" : "=l"(d) : "f"(x))
#define UNPK(lo, hi, v) asm("mov.b64 {%0, %1}, %2;" : "=f"(lo), "=f"(hi) : "l"(v))

// =====================================================================
// tiny precompute: wpe, folded bias
// =====================================================================
__global__ void prep_kernel(const float* __restrict__ W_pos, const float* __restrict__ b_pos,
                            const float* __restrict__ W1,    const float* __restrict__ b1) {
    int t = threadIdx.x; // 512 threads
    float s0 = 0.f, s1 = 0.f, sb = 0.f;
    for (int e = 0; e < 64; ++e) {
        float w = W1[(size_t)(64 + e) * HID_ + t];
        s0 += W_pos[e] * w;
        s1 += W_pos[64 + e] * w;
        sb += b_pos[e] * w;
    }
    g_wpe[t] = s0;
    g_wpe[HID_ + t] = s1;
    g_b1p[t] = b1[t] + sb;
}

// =====================================================================
// ranks: sel[s,i,m] = #{ j : d_j<d_m or (d_j==d_m and j<m) }  (stable argsort^2)
// one warp per ped i; exact fp32 replica of sqrt(dx*dx+dy*dy), no fma
// =====================================================================
__device__ __forceinline__ float distf(const float* px, const float* py,
                                       int j, float xi, float yi) {
    float dx = px[j] - xi;
    float dy = py[j] - yi;
    return __fsqrt_rn(__fadd_rn(__fmul_rn(dx, dx), __fmul_rn(dy, dy)));
}

__global__ void rank_kernel(const float* __restrict__ lp) {
    int s = blockIdx.y;
    __shared__ float px[N_], py[N_];
    int tid = threadIdx.x;
    for (int j = tid; j < N_; j += 256) {
        px[j] = lp[(size_t)(s * N_ + j) * 2];
        py[j] = lp[(size_t)(s * N_ + j) * 2 + 1];
    }
    __syncthreads();
    int w = tid >> 5, lane = tid & 31;
    int i = blockIdx.x * 8 + w;
    float xi = px[i], yi = py[i];

    float dl = distf(px, py, lane, xi, yi);
    float dm[MAXC];
#pragma unroll
    for (int m = 0; m < MAXC; ++m) dm[m] = __shfl_sync(0xffffffffu, dl, m);

    int cnt[MAXC];
#pragma unroll
    for (int m = 0; m < MAXC; ++m) cnt[m] = 0;
    for (int j = lane; j < N_; j += 32) {
        float d = distf(px, py, j, xi, yi);
#pragma unroll
        for (int m = 0; m < MAXC; ++m)
            cnt[m] += (int)((d < dm[m]) || (d == dm[m] && j < m));
    }
    int myr = 0;
#pragma unroll
    for (int m = 0; m < MAXC; ++m) {
        int tot = __reduce_add_sync(0xffffffffu, cnt[m]);
        if (lane == m) myr = tot;
    }
    if (lane < MAXC) g_sel[(s * N_ + i) * MAXC + lane] = myr;
}

// =====================================================================
// Y = h @ W1[0:64,:]   (50000x64 @ 64x512), 64x64 tiles, 256 thr, 4x4 reg tile
// =====================================================================
__global__ void y_kernel(const float* __restrict__ h, const float* __restrict__ W1) {
    __shared__ __align__(16) float Ash[64 * 65];
    __shared__ __align__(16) float Bsh[64 * 64];
    int tid = threadIdx.x;
    int row0 = blockIdx.x * 64;
    int c0   = blockIdx.y * 64;
#pragma unroll
    for (int q = 0; q < 4; ++q) {
        int idx4 = tid + 256 * q;
        int row = idx4 >> 4, k4 = (idx4 & 15) << 2;
        float4 v = make_float4(0.f, 0.f, 0.f, 0.f);
        if (row0 + row < NPED) v = *(const float4*)&h[(size_t)(row0 + row) * H_ + k4];
        Ash[row * 65 + k4 + 0] = v.x; Ash[row * 65 + k4 + 1] = v.y;
        Ash[row * 65 + k4 + 2] = v.z; Ash[row * 65 + k4 + 3] = v.w;
    }
#pragma unroll
    for (int q = 0; q < 4; ++q) {
        int idx4 = tid + 256 * q;
        int k = idx4 >> 4, c4 = (idx4 & 15) << 2;
        *(float4*)&Bsh[k * 64 + c4] = *(const float4*)&W1[(size_t)k * HID_ + c0 + c4];
    }
    __syncthreads();
    int rg = tid >> 4, cg = tid & 15;
    float acc[4][4] = {};
#pragma unroll 16
    for (int k = 0; k < 64; ++k) {
        float a[4];
#pragma unroll
        for (int r = 0; r < 4; ++r) a[r] = Ash[(rg * 4 + r) * 65 + k];
        float4 b = *(const float4*)&Bsh[k * 64 + cg * 4];
#pragma unroll
        for (int r = 0; r < 4; ++r) {
            acc[r][0] += a[r] * b.x; acc[r][1] += a[r] * b.y;
            acc[r][2] += a[r] * b.z; acc[r][3] += a[r] * b.w;
        }
    }
#pragma unroll
    for (int r = 0; r < 4; ++r) {
        int row = row0 + rg * 4 + r;
        if (row < NPED)
            *(float4*)&g_Y[(size_t)row * HID_ + c0 + cg * 4] =
                make_float4(acc[r][0], acc[r][1], acc[r][2], acc[r][3]);
    }
}

// =====================================================================
// fused: gather + in-register layer1 + f32x2 layer2 GEMM + attention pool
// block = (s, 16 peds) -> 256 rows x 32 cols; 128 thr, 2 rows/thread.
// W2 resident in smem (broadcast reads); no barriers in the K mainloop.
// =====================================================================
// smem float offsets
#define O_W2   0        // 16384 (reused by X2 256x33=8448 + wsh 256)
#define O_WP0  16384    // 512
#define O_WP1  16896    // 512
#define O_B1P  17408    // 512
#define O_PX   17920    // 200
#define O_PY   18120    // 200
#define O_B2   18320    // 32
#define O_BAT  18352    // 16
#define SM_FLOATS 18368

__global__ __launch_bounds__(128) void fused_kernel(
    const float* __restrict__ lp, const float* __restrict__ W2g,
    const float* __restrict__ b2g, const float* __restrict__ Wag,
    const float* __restrict__ bag, float* __restrict__ out) {
    extern __shared__ __align__(16) float sm[];
    float* W2s  = sm + O_W2;
    float* wp0s = sm + O_WP0;
    float* wp1s = sm + O_WP1;
    float* b1ps = sm + O_B1P;
    float* px   = sm + O_PX;
    float* py   = sm + O_PY;
    float* b2s  = sm + O_B2;
    float* bats = sm + O_BAT;

    const int tid = threadIdx.x;
    const int s   = blockIdx.y;
    const int pg  = blockIdx.x;          // 16-ped group (0..12, last partial)
    const int base = s * N_;

    // ---- stage constants ----
#pragma unroll
    for (int q = 0; q < 32; ++q)   // W2: 4096 float4
        *(float4*)&W2s[(tid + q * 128) * 4] = *(const float4*)&W2g[(size_t)(tid + q * 128) * 4];
    for (int k = tid; k < HID_; k += 128) {
        wp0s[k] = g_wpe[k];
        wp1s[k] = g_wpe[HID_ + k];
        b1ps[k] = g_b1p[k];
    }
    for (int j = tid; j < N_; j += 128) {
        float2 p = *(const float2*)&lp[(size_t)(base + j) * 2];
        px[j] = p.x; py[j] = p.y;
    }
    if (tid < BN_)  b2s[tid]  = b2g[tid];
    if (tid < MAXC) bats[tid] = bag[tid];
    __syncthreads();

    // ---- per-row gather info (rows r0=tid, r1=tid+128; row = ped*16+m) ----
    const float *yp0, *yp1;
    float fx0, fy0, fx1, fy1;
    {
        int p = tid >> 4, m = tid & 15;
        int i0 = min(pg * 16 + p, N_ - 1);
        int i1 = min(pg * 16 + p + 8, N_ - 1);
        int rk0 = g_sel[(base + i0) * MAXC + m];
        int rk1 = g_sel[(base + i1) * MAXC + m];
        yp0 = g_Y + (size_t)(base + rk0) * HID_;
        yp1 = g_Y + (size_t)(base + rk1) * HID_;
        fx0 = px[rk0] - px[i0];  fy0 = py[rk0] - py[i0];
        fx1 = px[rk1] - px[i1];  fy1 = py[rk1] - py[i1];
    }

    // ---- mainloop: K=512, barrier-free ----
    unsigned long long acc0[16], acc1[16];
#pragma unroll
    for (int c = 0; c < 16; ++c) { acc0[c] = 0ULL; acc1[c] = 0ULL; }

#pragma unroll 2
    for (int k = 0; k < HID_; k += 4) {
        float4 y0 = *(const float4*)(yp0 + k);
        float4 y1 = *(const float4*)(yp1 + k);
        float4 w0 = *(const float4*)&wp0s[k];
        float4 w1 = *(const float4*)&wp1s[k];
        float4 bb = *(const float4*)&b1ps[k];
        float x0[4], x1[4];
        x0[0] = fmaxf(fmaf(fx0, w0.x, fmaf(fy0, w1.x, y0.x + bb.x)), 0.f);
        x0[1] = fmaxf(fmaf(fx0, w0.y, fmaf(fy0, w1.y, y0.y + bb.y)), 0.f);
        x0[2] = fmaxf(fmaf(fx0, w0.z, fmaf(fy0, w1.z, y0.z + bb.z)), 0.f);
        x0[3] = fmaxf(fmaf(fx0, w0.w, fmaf(fy0, w1.w, y0.w + bb.w)), 0.f);
        x1[0] = fmaxf(fmaf(fx1, w0.x, fmaf(fy1, w1.x, y1.x + bb.x)), 0.f);
        x1[1] = fmaxf(fmaf(fx1, w0.y, fmaf(fy1, w1.y, y1.y + bb.y)), 0.f);
        x1[2] = fmaxf(fmaf(fx1, w0.z, fmaf(fy1, w1.z, y1.z + bb.z)), 0.f);
        x1[3] = fmaxf(fmaf(fx1, w0.w, fmaf(fy1, w1.w, y1.w + bb.w)), 0.f);
#pragma unroll
        for (int kk = 0; kk < 4; ++kk) {
            unsigned long long a0, a1;
            PACK_DUP(a0, x0[kk]);
            PACK_DUP(a1, x1[kk]);
            const ulonglong2* wrow = (const ulonglong2*)&W2s[(k + kk) * 32];
#pragma unroll
            for (int q = 0; q < 8; ++q) {
                ulonglong2 b = wrow[q];       // LDS.128 broadcast
                FMA2(acc0[2 * q],     a0, b.x);
                FMA2(acc0[2 * q + 1], a0, b.y);
                FMA2(acc1[2 * q],     a1, b.x);
                FMA2(acc1[2 * q + 1], a1, b.y);
            }
        }
    }

    __syncthreads();   // all W2s reads done -> safe to overwrite with X2

    // ---- X2 = relu(acc + b2), stride 33, rows tid / tid+128 ----
    float* X2  = sm;           // 256*33 = 8448
    float* wsh = sm + 8448;    // 256
#pragma unroll
    for (int cp = 0; cp < 16; ++cp) {
        float lo, hi;
        UNPK(lo, hi, acc0[cp]);
        X2[tid * 33 + 2 * cp]     = fmaxf(lo + b2s[2 * cp], 0.f);
        X2[tid * 33 + 2 * cp + 1] = fmaxf(hi + b2s[2 * cp + 1], 0.f);
        UNPK(lo, hi, acc1[cp]);
        X2[(tid + 128) * 33 + 2 * cp]     = fmaxf(lo + b2s[2 * cp], 0.f);
        X2[(tid + 128) * 33 + 2 * cp + 1] = fmaxf(hi + b2s[2 * cp + 1], 0.f);
    }
    __syncthreads();

    // ---- logits + softmax (two peds per thread: p and p+8) ----
    {
        int p = tid >> 4, t = tid & 15;
        float lg0 = bats[t], lg1 = bats[t];
        const float* wa = Wag + t;
#pragma unroll 4
        for (int k = 0; k < 512; ++k) {
            int m = k >> 5, c = k & 31;
            float w = __ldg(&wa[k * 16]);
            lg0 = fmaf(X2[(p * 16 + m) * 33 + c], w, lg0);
            lg1 = fmaf(X2[((p + 8) * 16 + m) * 33 + c], w, lg1);
        }
        float mx0 = lg0, mx1 = lg1;
#pragma unroll
        for (int o = 8; o; o >>= 1) {
            mx0 = fmaxf(mx0, __shfl_xor_sync(0xffffffffu, mx0, o, 16));
            mx1 = fmaxf(mx1, __shfl_xor_sync(0xffffffffu, mx1, o, 16));
        }
        float e0 = expf(lg0 - mx0), e1 = expf(lg1 - mx1);
        float s0 = e0, s1 = e1;
#pragma unroll
        for (int o = 8; o; o >>= 1) {
            s0 += __shfl_xor_sync(0xffffffffu, s0, o, 16);
            s1 += __shfl_xor_sync(0xffffffffu, s1, o, 16);
        }
        wsh[p * 16 + t]       = e0 / s0;
        wsh[(p + 8) * 16 + t] = e1 / s1;
    }
    __syncthreads();

    // ---- weighted pool: 16 peds x 32 cols ----
    for (int o = tid; o < 512; o += 128) {
        int pp = o >> 5, c = o & 31;
        int gp = pg * 16 + pp;
        if (gp < N_) {
            float a = 0.f;
#pragma unroll
            for (int m = 0; m < MAXC; ++m)
                a = fmaf(X2[(pp * 16 + m) * 33 + c], wsh[pp * 16 + m], a);
            out[(size_t)(base + gp) * BN_ + c] = a;
        }
    }
}

extern "C" void kernel_launch(void* const* d_in, const int* in_sizes, int n_in,
                              void* d_out, int out_size) {
    const float* h_st  = (const float*)d_in[0];
    const float* lp    = (const float*)d_in[1];
    const float* W_pos = (const float*)d_in[2];
    const float* b_pos = (const float*)d_in[3];
    const float* W1    = (const float*)d_in[4];
    const float* b1    = (const float*)d_in[5];
    const float* W2    = (const float*)d_in[6];
    const float* b2    = (const float*)d_in[7];
    const float* Wa    = (const float*)d_in[8];
    const float* ba    = (const float*)d_in[9];
    float* out = (float*)d_out;

    cudaFuncSetAttribute(fused_kernel, cudaFuncAttributeMaxDynamicSharedMemorySize,
                         SM_FLOATS * (int)sizeof(float));

    prep_kernel<<<1, HID_>>>(W_pos, b_pos, W1, b1);
    rank_kernel<<<dim3(N_ / 8, S_), 256>>>(lp);
    y_kernel<<<dim3((NPED + 63) / 64, HID_ / 64), 256>>>(h_st, W1);
    fused_kernel<<<dim3(13, S_), 128, SM_FLOATS * (int)sizeof(float)>>>(
        lp, W2, b2, Wa, ba, out);
}